// round 12
// baseline (speedup 1.0000x reference)
#include <cuda_runtime.h>
#include <cstdint>

#define TSEQ 2048
#define DMOD 1024
#define NH   16
#define DH   64
#define TRI  3072   // 3*DMOD

// Scratch (device globals: allocation-free)
__device__ float g_qkv[TSEQ * TRI];   // [t][h*192 + {q:0,k:64,v:128} + d]
__device__ float g_oh [TSEQ * DMOD];  // attention output, heads concatenated

// ---------------------------------------------------------------------------
// SGEMM: C[M,N] = A[M,K] @ B[K,N] + bias[N]
// 128x128 tile, BK=8, 256 threads, 8x8 per thread, warp strip 32x64,
// register-staged prefetch.
// ---------------------------------------------------------------------------
__global__ __launch_bounds__(256)
void sgemm_bias_kernel(const float* __restrict__ A, const float* __restrict__ B,
                       const float* __restrict__ bias, float* __restrict__ C,
                       int M, int N, int K)
{
    __shared__ float As[8][128];   // A transposed: As[k][m]
    __shared__ float Bs[8][128];   // Bs[k][n]

    const int tid = threadIdx.x;
    const int m0 = blockIdx.y * 128;
    const int n0 = blockIdx.x * 128;

    // loaders
    const int arow = tid >> 1;            // 0..127
    const int akc  = (tid & 1) << 2;      // 0 or 4
    const int bkr  = tid >> 5;            // 0..7
    const int bnc  = (tid & 31) << 2;     // 0..124

    const float* Aptr = A + (size_t)(m0 + arow) * K + akc;
    const float* Bptr = B + (size_t)bkr * N + n0 + bnc;

    // compute mapping: warp -> 32x64 strip
    const int w = tid >> 5, l = tid & 31;
    const int wr = w >> 1, wc = w & 1;
    const int lr = l >> 3, lc = l & 7;
    const int r0 = wr * 32 + lr * 4;      // rows r0..r0+3, r0+16..r0+19
    const int c0 = wc * 64 + lc * 4;      // cols c0..c0+3, c0+32..c0+35

    float acc[8][8];
#pragma unroll
    for (int i = 0; i < 8; i++)
#pragma unroll
        for (int j = 0; j < 8; j++) acc[i][j] = 0.f;

    float4 aReg = *(const float4*)Aptr;
    float4 bReg = *(const float4*)Bptr;

    const int nk = K >> 3;
    for (int kbk = 0; kbk < nk; kbk++) {
        As[akc + 0][arow] = aReg.x;
        As[akc + 1][arow] = aReg.y;
        As[akc + 2][arow] = aReg.z;
        As[akc + 3][arow] = aReg.w;
        *(float4*)&Bs[bkr][bnc] = bReg;
        __syncthreads();
        if (kbk + 1 < nk) {
            aReg = *(const float4*)(Aptr + (kbk + 1) * 8);
            bReg = *(const float4*)(Bptr + (size_t)(kbk + 1) * 8 * N);
        }
#pragma unroll
        for (int kk = 0; kk < 8; kk++) {
            float4 a0 = *(const float4*)&As[kk][r0];
            float4 a1 = *(const float4*)&As[kk][r0 + 16];
            float4 b0 = *(const float4*)&Bs[kk][c0];
            float4 b1 = *(const float4*)&Bs[kk][c0 + 32];
            float av[8] = {a0.x, a0.y, a0.z, a0.w, a1.x, a1.y, a1.z, a1.w};
            float bv[8] = {b0.x, b0.y, b0.z, b0.w, b1.x, b1.y, b1.z, b1.w};
#pragma unroll
            for (int i = 0; i < 8; i++)
#pragma unroll
                for (int j = 0; j < 8; j++)
                    acc[i][j] = fmaf(av[i], bv[j], acc[i][j]);
        }
        __syncthreads();
    }

#pragma unroll
    for (int i = 0; i < 8; i++) {
        const int r = m0 + r0 + ((i < 4) ? i : (12 + i));   // i>=4 -> +16+(i-4)
#pragma unroll
        for (int jj = 0; jj < 2; jj++) {
            const int c = n0 + c0 + jj * 32;
            float4 bb = *(const float4*)(bias + c);
            float4 v;
            v.x = acc[i][jj * 4 + 0] + bb.x;
            v.y = acc[i][jj * 4 + 1] + bb.y;
            v.z = acc[i][jj * 4 + 2] + bb.z;
            v.w = acc[i][jj * 4 + 3] + bb.w;
            *(float4*)(C + (size_t)r * N + c) = v;
        }
    }
}

// ---------------------------------------------------------------------------
// k_out / v_out permute:  k_out[t][h*64+d] = qkv[t][h*192+64+d], v: +128
// ---------------------------------------------------------------------------
__global__ void kv_permute_kernel(const float* __restrict__ qkv,
                                  float* __restrict__ kout,
                                  float* __restrict__ vout)
{
    int idx = blockIdx.x * blockDim.x + threadIdx.x;
    if (idx >= TSEQ * DMOD) return;
    int t = idx >> 10;
    int col = idx & 1023;
    int h = col >> 6;
    int d = col & 63;
    const float* row = qkv + (size_t)t * TRI + h * 192;
    kout[idx] = row[64 + d];
    vout[idx] = row[128 + d];
}

// ---------------------------------------------------------------------------
// Fused causal attention with per-head shift bias (flash-attention style).
// One CTA = (head, 64-query tile). 256 threads; warp owns 8 q-rows;
// thread computes a 4x4 sub-tile. Q,K stored d-major with XOR group swizzle.
// ---------------------------------------------------------------------------
#define ASTR 68
#define AT_SMEM (4 * 64 * ASTR * 4)

__global__ __launch_bounds__(256)
void attn_kernel(const float* __restrict__ qkv, const float* __restrict__ shift,
                 float* __restrict__ oh)
{
    extern __shared__ float sm[];
    float* QsT = sm;                  // [d][c] swizzled, 64x68
    float* KsT = sm + 64 * ASTR;      // [d][c] swizzled
    float* Vs  = sm + 2 * 64 * ASTR;  // [k][d] natural
    float* Ps  = sm + 3 * 64 * ASTR;  // [r][k] natural

    const int bid = blockIdx.x;
    const int h  = bid & (NH - 1);
    const int qt = 31 - (bid >> 4);       // big q-tiles first (load balance)
    const int q0 = qt * 64;

    const float hscale = exp2f(-0.5f * (float)h);   // exp(-ln2 * h/2)

    const int tid  = threadIdx.x;
    const int w    = tid >> 5, l = tid & 31;
    const int lrow = l >> 4;              // 0..1
    const int lcol = l & 15;              // 0..15
    const int rbase = w * 8 + lrow * 4;   // this thread's 4 q-rows
    const int cbase = lcol * 4;           // this thread's 4 cols
    const int agrp  = rbase >> 2;

    // loader indices: 16 d-groups x 16 tokens per pass, 4 passes
    const int dchunk = tid & 15;
    const int crow0  = tid >> 4;

    const float* qb = qkv + h * 192;
    const float* kbp = qb + 64;
    const float* vbp = qb + 128;

    // ---- load Q^T (swizzled) ----
#pragma unroll
    for (int it = 0; it < 4; it++) {
        int c = crow0 + it * 16;
        float4 v = *(const float4*)(qb + (size_t)(q0 + c) * TRI + dchunk * 4);
        int pg = ((c >> 2) ^ dchunk) << 2;
        int base = dchunk * 4 * ASTR + pg + (c & 3);
        QsT[base]            = v.x;
        QsT[base + ASTR]     = v.y;
        QsT[base + 2 * ASTR] = v.z;
        QsT[base + 3 * ASTR] = v.w;
    }

    float o[4][4];
    float mrun[4], lrun[4];
#pragma unroll
    for (int i = 0; i < 4; i++) {
        mrun[i] = -1e30f; lrun[i] = 0.f;
#pragma unroll
        for (int j = 0; j < 4; j++) o[i][j] = 0.f;
    }

    for (int kt = 0; kt <= qt; kt++) {
        const int k0 = kt * 64;
        __syncthreads();   // prev PV reads of Vs/Ps, prev S reads of KsT done

        // ---- load K^T (swizzled) + V (natural) ----
#pragma unroll
        for (int it = 0; it < 4; it++) {
            int c = crow0 + it * 16;
            float4 kv = *(const float4*)(kbp + (size_t)(k0 + c) * TRI + dchunk * 4);
            float4 vv = *(const float4*)(vbp + (size_t)(k0 + c) * TRI + dchunk * 4);
            int pg = ((c >> 2) ^ dchunk) << 2;
            int base = dchunk * 4 * ASTR + pg + (c & 3);
            KsT[base]            = kv.x;
            KsT[base + ASTR]     = kv.y;
            KsT[base + 2 * ASTR] = kv.z;
            KsT[base + 3 * ASTR] = kv.w;
            *(float4*)(Vs + (size_t)c * ASTR + dchunk * 4) = vv;
        }
        __syncthreads();

        // ---- S = Q K^T ----
        float s[4][4];
#pragma unroll
        for (int i = 0; i < 4; i++)
#pragma unroll
            for (int j = 0; j < 4; j++) s[i][j] = 0.f;

#pragma unroll 4
        for (int d = 0; d < 64; d++) {
            int sw = d >> 2;
            float4 a = *(const float4*)(QsT + d * ASTR + ((agrp ^ sw) << 2));
            float4 b = *(const float4*)(KsT + d * ASTR + ((lcol ^ sw) << 2));
            float av[4] = {a.x, a.y, a.z, a.w};
            float bv[4] = {b.x, b.y, b.z, b.w};
#pragma unroll
            for (int i = 0; i < 4; i++)
#pragma unroll
                for (int j = 0; j < 4; j++)
                    s[i][j] = fmaf(av[i], bv[j], s[i][j]);
        }

        // ---- scale 1/sqrt(64), per-head shift bias, causal mask ----
#pragma unroll
        for (int i = 0; i < 4; i++) {
            int gq = q0 + rbase + i;
            float4 sh = *(const float4*)(shift + (size_t)gq * TSEQ + k0 + cbase);
            float shv[4] = {sh.x, sh.y, sh.z, sh.w};
#pragma unroll
            for (int j = 0; j < 4; j++) {
                int gk = k0 + cbase + j;
                float val = fmaf(s[i][j], 0.125f, -hscale * shv[j]);
                s[i][j] = (gk > gq) ? -1e30f : val;
            }
        }

        // ---- online softmax (rows are warp-local: shuffle over lcol bits) ----
#pragma unroll
        for (int i = 0; i < 4; i++) {
            float tm = fmaxf(fmaxf(s[i][0], s[i][1]), fmaxf(s[i][2], s[i][3]));
            tm = fmaxf(tm, __shfl_xor_sync(0xffffffffu, tm, 1));
            tm = fmaxf(tm, __shfl_xor_sync(0xffffffffu, tm, 2));
            tm = fmaxf(tm, __shfl_xor_sync(0xffffffffu, tm, 4));
            tm = fmaxf(tm, __shfl_xor_sync(0xffffffffu, tm, 8));
            float mnew = fmaxf(mrun[i], tm);
            float alpha = __expf(mrun[i] - mnew);
            float rs = 0.f;
#pragma unroll
            for (int j = 0; j < 4; j++) {
                float p = __expf(s[i][j] - mnew);
                s[i][j] = p;
                rs += p;
            }
            rs += __shfl_xor_sync(0xffffffffu, rs, 1);
            rs += __shfl_xor_sync(0xffffffffu, rs, 2);
            rs += __shfl_xor_sync(0xffffffffu, rs, 4);
            rs += __shfl_xor_sync(0xffffffffu, rs, 8);
            lrun[i] = lrun[i] * alpha + rs;
            mrun[i] = mnew;
#pragma unroll
            for (int j = 0; j < 4; j++) o[i][j] *= alpha;
        }

        // ---- P -> smem ----
#pragma unroll
        for (int i = 0; i < 4; i++)
            *(float4*)(Ps + (size_t)(rbase + i) * ASTR + cbase) =
                make_float4(s[i][0], s[i][1], s[i][2], s[i][3]);
        __syncthreads();

        // ---- O += P @ V ----
#pragma unroll 4
        for (int k4 = 0; k4 < 64; k4 += 4) {
            float4 pa0 = *(const float4*)(Ps + (size_t)(rbase + 0) * ASTR + k4);
            float4 pa1 = *(const float4*)(Ps + (size_t)(rbase + 1) * ASTR + k4);
            float4 pa2 = *(const float4*)(Ps + (size_t)(rbase + 2) * ASTR + k4);
            float4 pa3 = *(const float4*)(Ps + (size_t)(rbase + 3) * ASTR + k4);
            float pm[4][4] = {
                {pa0.x, pa0.y, pa0.z, pa0.w},
                {pa1.x, pa1.y, pa1.z, pa1.w},
                {pa2.x, pa2.y, pa2.z, pa2.w},
                {pa3.x, pa3.y, pa3.z, pa3.w}};
#pragma unroll
            for (int kk = 0; kk < 4; kk++) {
                float4 b = *(const float4*)(Vs + (size_t)(k4 + kk) * ASTR + cbase);
                float bv[4] = {b.x, b.y, b.z, b.w};
#pragma unroll
                for (int i = 0; i < 4; i++) {
                    float p = pm[i][kk];
#pragma unroll
                    for (int j = 0; j < 4; j++)
                        o[i][j] = fmaf(p, bv[j], o[i][j]);
                }
            }
        }
    }

    // ---- finalize and write head output ----
#pragma unroll
    for (int i = 0; i < 4; i++) {
        float inv = 1.f / lrun[i];
        int gq = q0 + rbase + i;
        float4 v = make_float4(o[i][0] * inv, o[i][1] * inv,
                               o[i][2] * inv, o[i][3] * inv);
        *(float4*)(oh + (size_t)gq * DMOD + h * DH + cbase) = v;
    }
}

// ---------------------------------------------------------------------------
extern "C" void kernel_launch(void* const* d_in, const int* in_sizes, int n_in,
                              void* d_out, int out_size)
{
    (void)in_sizes; (void)n_in; (void)out_size;

    const float* x     = (const float*)d_in[0];
    // d_in[1] = mask: always causal tril by construction -> computed from indices
    const float* shift = (const float*)d_in[2];
    const float* W     = (const float*)d_in[3];
    const float* b     = (const float*)d_in[4];
    const float* Wo    = (const float*)d_in[5];
    const float* bo    = (const float*)d_in[6];

    float* out   = (float*)d_out;
    float* o_out = out;
    float* k_out = out + (size_t)TSEQ * DMOD;
    float* v_out = out + 2 * (size_t)TSEQ * DMOD;

    float *qkv = nullptr, *oh = nullptr;
    cudaGetSymbolAddress((void**)&qkv, g_qkv);
    cudaGetSymbolAddress((void**)&oh,  g_oh);

    cudaFuncSetAttribute(attn_kernel,
                         cudaFuncAttributeMaxDynamicSharedMemorySize, AT_SMEM);

    // 1) qkv = x @ W + b
    sgemm_bias_kernel<<<dim3(TRI / 128, TSEQ / 128), 256>>>(
        x, W, b, qkv, TSEQ, TRI, DMOD);

    // 2) k_out / v_out permute
    kv_permute_kernel<<<(TSEQ * DMOD + 255) / 256, 256>>>(qkv, k_out, v_out);

    // 3) fused causal attention with shift bias
    attn_kernel<<<NH * (TSEQ / 64), 256, AT_SMEM>>>(qkv, shift, oh);

    // 4) o = oh @ Wo + bo
    sgemm_bias_kernel<<<dim3(DMOD / 128, TSEQ / 128), 256>>>(
        oh, Wo, bo, o_out, TSEQ, DMOD, DMOD);
}

// round 16
// speedup vs baseline: 1.4507x; 1.4507x over previous
#include <cuda_runtime.h>
#include <cuda_bf16.h>
#include <cstdint>

#define TSEQ 2048
#define DMOD 1024
#define NH   16
#define DH   64
#define TRI  3072   // 3*DMOD

// ---------------------------------------------------------------------------
// Scratch (device globals: allocation-free)
// ---------------------------------------------------------------------------
__device__ float g_qkv[TSEQ * TRI];   // [t][h*192 + {q:0,k:64,v:128} + d]
__device__ float g_oh [TSEQ * DMOD];  // attention output, heads concatenated

__device__ __nv_bfloat16 g_xhi [TSEQ * DMOD];
__device__ __nv_bfloat16 g_xlo [TSEQ * DMOD];
__device__ __nv_bfloat16 g_wthi[TRI  * DMOD];   // W^T split: [n][k]
__device__ __nv_bfloat16 g_wtlo[TRI  * DMOD];
__device__ __nv_bfloat16 g_wohi[DMOD * DMOD];   // Wo^T split: [n][k]
__device__ __nv_bfloat16 g_wolo[DMOD * DMOD];
__device__ __nv_bfloat16 g_ohhi[TSEQ * DMOD];
__device__ __nv_bfloat16 g_ohlo[TSEQ * DMOD];

// ---------------------------------------------------------------------------
// helpers
// ---------------------------------------------------------------------------
__device__ __forceinline__ uint32_t smem_u32(const void* p) {
    uint32_t a;
    asm("{ .reg .u64 t; cvta.to.shared.u64 t, %1; cvt.u32.u64 %0, t; }"
        : "=r"(a) : "l"(p));
    return a;
}

#define SW128(off) ((off) ^ (((off) >> 3) & 0x70))

#define CP_ASYNC16(saddr, gptr) \
    asm volatile("cp.async.cg.shared.global [%0], [%1], 16;" \
                 :: "r"((uint32_t)(saddr)), "l"(gptr) : "memory")
#define CP_COMMIT() asm volatile("cp.async.commit_group;" ::: "memory")
#define CP_WAIT(n)  asm volatile("cp.async.wait_group %0;" :: "n"(n) : "memory")

__device__ __forceinline__ void ldsm_x4(uint32_t* r, uint32_t addr) {
    asm volatile("ldmatrix.sync.aligned.m8n8.x4.shared.b16 {%0,%1,%2,%3}, [%4];"
                 : "=r"(r[0]), "=r"(r[1]), "=r"(r[2]), "=r"(r[3]) : "r"(addr));
}

__device__ __forceinline__ void mma_bf16(float* c, const uint32_t* a,
                                         const uint32_t* b) {
    asm volatile(
        "mma.sync.aligned.m16n8k16.row.col.f32.bf16.bf16.f32 "
        "{%0,%1,%2,%3}, {%4,%5,%6,%7}, {%8,%9}, {%0,%1,%2,%3};"
        : "+f"(c[0]), "+f"(c[1]), "+f"(c[2]), "+f"(c[3])
        : "r"(a[0]), "r"(a[1]), "r"(a[2]), "r"(a[3]), "r"(b[0]), "r"(b[1]));
}

// ---------------------------------------------------------------------------
// Split fp32 -> bf16 hi/lo (elementwise, same layout)
// ---------------------------------------------------------------------------
__global__ void split_kernel(const float* __restrict__ in,
                             __nv_bfloat16* __restrict__ hi,
                             __nv_bfloat16* __restrict__ lo, int n)
{
    int i = (blockIdx.x * blockDim.x + threadIdx.x) * 4;
    if (i >= n) return;
    float4 v = *(const float4*)(in + i);
    __nv_bfloat16 h0 = __float2bfloat16(v.x);
    __nv_bfloat16 h1 = __float2bfloat16(v.y);
    __nv_bfloat16 h2 = __float2bfloat16(v.z);
    __nv_bfloat16 h3 = __float2bfloat16(v.w);
    __nv_bfloat162* hp = (__nv_bfloat162*)(hi + i);
    __nv_bfloat162* lp = (__nv_bfloat162*)(lo + i);
    hp[0] = __nv_bfloat162(h0, h1);
    hp[1] = __nv_bfloat162(h2, h3);
    lp[0] = __nv_bfloat162(__float2bfloat16(v.x - __bfloat162float(h0)),
                           __float2bfloat16(v.y - __bfloat162float(h1)));
    lp[1] = __nv_bfloat162(__float2bfloat16(v.z - __bfloat162float(h2)),
                           __float2bfloat16(v.w - __bfloat162float(h3)));
}

// ---------------------------------------------------------------------------
// Transpose + split: in[K][N] fp32 -> out_hi/lo[N][K] bf16
// ---------------------------------------------------------------------------
__global__ void transpose_split_kernel(const float* __restrict__ in,
                                       __nv_bfloat16* __restrict__ ohi,
                                       __nv_bfloat16* __restrict__ olo,
                                       int K, int N)
{
    __shared__ float t[32][33];
    const int bx = blockIdx.x * 32;   // N offset
    const int by = blockIdx.y * 32;   // K offset
    const int x = threadIdx.x, y = threadIdx.y;  // (32, 8)
#pragma unroll
    for (int j = 0; j < 32; j += 8)
        t[y + j][x] = in[(size_t)(by + y + j) * N + bx + x];
    __syncthreads();
#pragma unroll
    for (int j = 0; j < 32; j += 8) {
        float v = t[x][y + j];
        __nv_bfloat16 h = __float2bfloat16(v);
        size_t o = (size_t)(bx + y + j) * K + by + x;
        ohi[o] = h;
        olo[o] = __float2bfloat16(v - __bfloat162float(h));
    }
}

// ---------------------------------------------------------------------------
// HMMA split-bf16 GEMM: C[M,N] = A[M,K] @ Bt[N,K]^T + bias
// CTA: 128x128 tile, BK=64, 2-stage cp.async pipeline, 8 warps (2x4),
// warp tile 64x32, m16n8k16 bf16 MMAs, 3 passes (hi*hi + hi*lo + lo*hi).
// ---------------------------------------------------------------------------
#define G_STAGE (4 * 128 * 64 * 2)        // Ahi,Alo,Bhi,Blo per stage (bytes)
#define G_SMEM  (2 * G_STAGE)             // 131072

__global__ __launch_bounds__(256, 1)
void gemm_hmma_kernel(const __nv_bfloat16* __restrict__ Ahi,
                      const __nv_bfloat16* __restrict__ Alo,
                      const __nv_bfloat16* __restrict__ Bhi,
                      const __nv_bfloat16* __restrict__ Blo,
                      const float* __restrict__ bias,
                      float* __restrict__ C, int M, int N, int K)
{
    extern __shared__ __align__(1024) char smem[];
    const uint32_t sb = smem_u32(smem);

    const int tid  = threadIdx.x;
    const int w    = tid >> 5;
    const int lane = tid & 31;
    const int m0 = blockIdx.y * 128;
    const int n0 = blockIdx.x * 128;

    const int warpM = (w >> 2) * 64;   // 0 / 64
    const int warpN = (w & 3) * 32;    // 0..96

    // ldmatrix per-lane addressing
    const int a_row  = lane & 15;
    const int a_cb   = (lane >> 4) * 16;
    const int b_row  = (lane & 7) + ((lane >> 4) << 3);
    const int b_cb   = ((lane >> 3) & 1) * 16;

    constexpr uint32_t TILE = 128 * 64 * 2;  // 16384 bytes

    float acc[4][4][4];
#pragma unroll
    for (int i = 0; i < 4; i++)
#pragma unroll
        for (int j = 0; j < 4; j++)
#pragma unroll
            for (int q = 0; q < 4; q++) acc[i][j][q] = 0.f;

    const int NK = K >> 6;

    // ---- stage loader ----
    auto load_stage = [&](int chunk, int st) {
        const uint32_t base = sb + st * G_STAGE;
        const int kc = chunk << 6;
#pragma unroll
        for (int it = 0; it < 4; it++) {
            int idx = tid + it * 256;          // 0..1023
            int r = idx >> 3, c = idx & 7;
            uint32_t sw = SW128((uint32_t)(r * 128 + c * 16));
            size_t ga = (size_t)(m0 + r) * K + kc + c * 8;
            size_t gb = (size_t)(n0 + r) * K + kc + c * 8;
            CP_ASYNC16(base + sw,            Ahi + ga);
            CP_ASYNC16(base + TILE + sw,     Alo + ga);
            CP_ASYNC16(base + 2 * TILE + sw, Bhi + gb);
            CP_ASYNC16(base + 3 * TILE + sw, Blo + gb);
        }
        CP_COMMIT();
    };

    load_stage(0, 0);

    for (int i = 0; i < NK; i++) {
        const int st = i & 1;
        if (i + 1 < NK) {
            load_stage(i + 1, st ^ 1);
            CP_WAIT(1);
        } else {
            CP_WAIT(0);
        }
        __syncthreads();

        const uint32_t base = sb + st * G_STAGE;
        const uint32_t sAhi = base;
        const uint32_t sAlo = base + TILE;
        const uint32_t sBhi = base + 2 * TILE;
        const uint32_t sBlo = base + 3 * TILE;

#pragma unroll
        for (int ks = 0; ks < 4; ks++) {
            const int kb = ks * 32;
            uint32_t ah[4][4], al[4][4], bh[2][4], bl[2][4];
#pragma unroll
            for (int mt = 0; mt < 4; mt++) {
                uint32_t off = SW128((uint32_t)((warpM + mt * 16 + a_row) * 128
                                                + kb + a_cb));
                ldsm_x4(ah[mt], sAhi + off);
                ldsm_x4(al[mt], sAlo + off);
            }
#pragma unroll
            for (int np = 0; np < 2; np++) {
                uint32_t off = SW128((uint32_t)((warpN + np * 16 + b_row) * 128
                                                + kb + b_cb));
                ldsm_x4(bh[np], sBhi + off);
                ldsm_x4(bl[np], sBlo + off);
            }
#pragma unroll
            for (int mt = 0; mt < 4; mt++)
#pragma unroll
                for (int nt = 0; nt < 4; nt++) {
                    const uint32_t* bhp = &bh[nt >> 1][(nt & 1) * 2];
                    const uint32_t* blp = &bl[nt >> 1][(nt & 1) * 2];
                    mma_bf16(acc[mt][nt], ah[mt], bhp);   // hi*hi
                    mma_bf16(acc[mt][nt], ah[mt], blp);   // hi*lo
                    mma_bf16(acc[mt][nt], al[mt], bhp);   // lo*hi
                }
        }
        __syncthreads();
    }

    // ---- epilogue: direct fp32 stores + bias ----
    const int er = lane >> 2;
    const int ec = (lane & 3) * 2;
#pragma unroll
    for (int mt = 0; mt < 4; mt++) {
        const int r0 = m0 + warpM + mt * 16 + er;
#pragma unroll
        for (int nt = 0; nt < 4; nt++) {
            const int c = n0 + warpN + nt * 8 + ec;
            float2 bv = *(const float2*)(bias + c);
            float2 v0 = make_float2(acc[mt][nt][0] + bv.x, acc[mt][nt][1] + bv.y);
            float2 v1 = make_float2(acc[mt][nt][2] + bv.x, acc[mt][nt][3] + bv.y);
            *(float2*)(C + (size_t)r0 * N + c)       = v0;
            *(float2*)(C + (size_t)(r0 + 8) * N + c) = v1;
        }
    }
}

// ---------------------------------------------------------------------------
// k_out / v_out permute:  k_out[t][h*64+d] = qkv[t][h*192+64+d], v: +128
// ---------------------------------------------------------------------------
__global__ void kv_permute_kernel(const float* __restrict__ qkv,
                                  float* __restrict__ kout,
                                  float* __restrict__ vout)
{
    int idx = blockIdx.x * blockDim.x + threadIdx.x;
    if (idx >= TSEQ * DMOD) return;
    int t = idx >> 10;
    int col = idx & 1023;
    int h = col >> 6;
    int d = col & 63;
    const float* row = qkv + (size_t)t * TRI + h * 192;
    kout[idx] = row[64 + d];
    vout[idx] = row[128 + d];
}

// ---------------------------------------------------------------------------
// Fused causal attention with per-head shift bias (flash-attention style).
// ---------------------------------------------------------------------------
#define ASTR 68
#define AT_SMEM (4 * 64 * ASTR * 4)

__global__ __launch_bounds__(256)
void attn_kernel(const float* __restrict__ qkv, const float* __restrict__ shift,
                 float* __restrict__ oh)
{
    extern __shared__ float sm[];
    float* QsT = sm;                  // [d][c] swizzled, 64x68
    float* KsT = sm + 64 * ASTR;      // [d][c] swizzled
    float* Vs  = sm + 2 * 64 * ASTR;  // [k][d] natural
    float* Ps  = sm + 3 * 64 * ASTR;  // [r][k] natural

    const int bid = blockIdx.x;
    const int h  = bid & (NH - 1);
    const int qt = 31 - (bid >> 4);       // big q-tiles first (load balance)
    const int q0 = qt * 64;

    const float hscale = exp2f(-0.5f * (float)h);   // exp(-ln2 * h/2)

    const int tid  = threadIdx.x;
    const int w    = tid >> 5, l = tid & 31;
    const int lrow = l >> 4;              // 0..1
    const int lcol = l & 15;              // 0..15
    const int rbase = w * 8 + lrow * 4;   // this thread's 4 q-rows
    const int cbase = lcol * 4;           // this thread's 4 cols
    const int agrp  = rbase >> 2;

    const int dchunk = tid & 15;
    const int crow0  = tid >> 4;

    const float* qb = qkv + h * 192;
    const float* kbp = qb + 64;
    const float* vbp = qb + 128;

    // ---- load Q^T (swizzled) ----
#pragma unroll
    for (int it = 0; it < 4; it++) {
        int c = crow0 + it * 16;
        float4 v = *(const float4*)(qb + (size_t)(q0 + c) * TRI + dchunk * 4);
        int pg = ((c >> 2) ^ dchunk) << 2;
        int base = dchunk * 4 * ASTR + pg + (c & 3);
        QsT[base]            = v.x;
        QsT[base + ASTR]     = v.y;
        QsT[base + 2 * ASTR] = v.z;
        QsT[base + 3 * ASTR] = v.w;
    }

    float o[4][4];
    float mrun[4], lrun[4];
#pragma unroll
    for (int i = 0; i < 4; i++) {
        mrun[i] = -1e30f; lrun[i] = 0.f;
#pragma unroll
        for (int j = 0; j < 4; j++) o[i][j] = 0.f;
    }

    for (int kt = 0; kt <= qt; kt++) {
        const int k0 = kt * 64;
        __syncthreads();

        // ---- load K^T (swizzled) + V (natural) ----
#pragma unroll
        for (int it = 0; it < 4; it++) {
            int c = crow0 + it * 16;
            float4 kv = *(const float4*)(kbp + (size_t)(k0 + c) * TRI + dchunk * 4);
            float4 vv = *(const float4*)(vbp + (size_t)(k0 + c) * TRI + dchunk * 4);
            int pg = ((c >> 2) ^ dchunk) << 2;
            int base = dchunk * 4 * ASTR + pg + (c & 3);
            KsT[base]            = kv.x;
            KsT[base + ASTR]     = kv.y;
            KsT[base + 2 * ASTR] = kv.z;
            KsT[base + 3 * ASTR] = kv.w;
            *(float4*)(Vs + (size_t)c * ASTR + dchunk * 4) = vv;
        }
        __syncthreads();

        // ---- S = Q K^T ----
        float s[4][4];
#pragma unroll
        for (int i = 0; i < 4; i++)
#pragma unroll
            for (int j = 0; j < 4; j++) s[i][j] = 0.f;

#pragma unroll 4
        for (int d = 0; d < 64; d++) {
            int sw = d >> 2;
            float4 a = *(const float4*)(QsT + d * ASTR + ((agrp ^ sw) << 2));
            float4 b = *(const float4*)(KsT + d * ASTR + ((lcol ^ sw) << 2));
            float av[4] = {a.x, a.y, a.z, a.w};
            float bv[4] = {b.x, b.y, b.z, b.w};
#pragma unroll
            for (int i = 0; i < 4; i++)
#pragma unroll
                for (int j = 0; j < 4; j++)
                    s[i][j] = fmaf(av[i], bv[j], s[i][j]);
        }

        // ---- scale, shift bias, causal mask ----
#pragma unroll
        for (int i = 0; i < 4; i++) {
            int gq = q0 + rbase + i;
            float4 sh = *(const float4*)(shift + (size_t)gq * TSEQ + k0 + cbase);
            float shv[4] = {sh.x, sh.y, sh.z, sh.w};
#pragma unroll
            for (int j = 0; j < 4; j++) {
                int gk = k0 + cbase + j;
                float val = fmaf(s[i][j], 0.125f, -hscale * shv[j]);
                s[i][j] = (gk > gq) ? -1e30f : val;
            }
        }

        // ---- online softmax ----
#pragma unroll
        for (int i = 0; i < 4; i++) {
            float tm = fmaxf(fmaxf(s[i][0], s[i][1]), fmaxf(s[i][2], s[i][3]));
            tm = fmaxf(tm, __shfl_xor_sync(0xffffffffu, tm, 1));
            tm = fmaxf(tm, __shfl_xor_sync(0xffffffffu, tm, 2));
            tm = fmaxf(tm, __shfl_xor_sync(0xffffffffu, tm, 4));
            tm = fmaxf(tm, __shfl_xor_sync(0xffffffffu, tm, 8));
            float mnew = fmaxf(mrun[i], tm);
            float alpha = __expf(mrun[i] - mnew);
            float rs = 0.f;
#pragma unroll
            for (int j = 0; j < 4; j++) {
                float p = __expf(s[i][j] - mnew);
                s[i][j] = p;
                rs += p;
            }
            rs += __shfl_xor_sync(0xffffffffu, rs, 1);
            rs += __shfl_xor_sync(0xffffffffu, rs, 2);
            rs += __shfl_xor_sync(0xffffffffu, rs, 4);
            rs += __shfl_xor_sync(0xffffffffu, rs, 8);
            lrun[i] = lrun[i] * alpha + rs;
            mrun[i] = mnew;
#pragma unroll
            for (int j = 0; j < 4; j++) o[i][j] *= alpha;
        }

        // ---- P -> smem ----
#pragma unroll
        for (int i = 0; i < 4; i++)
            *(float4*)(Ps + (size_t)(rbase + i) * ASTR + cbase) =
                make_float4(s[i][0], s[i][1], s[i][2], s[i][3]);
        __syncthreads();

        // ---- O += P @ V ----
#pragma unroll 4
        for (int k4 = 0; k4 < 64; k4 += 4) {
            float4 pa0 = *(const float4*)(Ps + (size_t)(rbase + 0) * ASTR + k4);
            float4 pa1 = *(const float4*)(Ps + (size_t)(rbase + 1) * ASTR + k4);
            float4 pa2 = *(const float4*)(Ps + (size_t)(rbase + 2) * ASTR + k4);
            float4 pa3 = *(const float4*)(Ps + (size_t)(rbase + 3) * ASTR + k4);
            float pm[4][4] = {
                {pa0.x, pa0.y, pa0.z, pa0.w},
                {pa1.x, pa1.y, pa1.z, pa1.w},
                {pa2.x, pa2.y, pa2.z, pa2.w},
                {pa3.x, pa3.y, pa3.z, pa3.w}};
#pragma unroll
            for (int kk = 0; kk < 4; kk++) {
                float4 b = *(const float4*)(Vs + (size_t)(k4 + kk) * ASTR + cbase);
                float bv[4] = {b.x, b.y, b.z, b.w};
#pragma unroll
                for (int i = 0; i < 4; i++) {
                    float p = pm[i][kk];
#pragma unroll
                    for (int j = 0; j < 4; j++)
                        o[i][j] = fmaf(p, bv[j], o[i][j]);
                }
            }
        }
    }

    // ---- finalize ----
#pragma unroll
    for (int i = 0; i < 4; i++) {
        float inv = 1.f / lrun[i];
        int gq = q0 + rbase + i;
        float4 v = make_float4(o[i][0] * inv, o[i][1] * inv,
                               o[i][2] * inv, o[i][3] * inv);
        *(float4*)(oh + (size_t)gq * DMOD + h * DH + cbase) = v;
    }
}

// ---------------------------------------------------------------------------
extern "C" void kernel_launch(void* const* d_in, const int* in_sizes, int n_in,
                              void* d_out, int out_size)
{
    (void)in_sizes; (void)n_in; (void)out_size;

    const float* x     = (const float*)d_in[0];
    // d_in[1] = mask: always causal tril by construction -> computed from indices
    const float* shift = (const float*)d_in[2];
    const float* W     = (const float*)d_in[3];
    const float* b     = (const float*)d_in[4];
    const float* Wo    = (const float*)d_in[5];
    const float* bo    = (const float*)d_in[6];

    float* out   = (float*)d_out;
    float* o_out = out;
    float* k_out = out + (size_t)TSEQ * DMOD;
    float* v_out = out + 2 * (size_t)TSEQ * DMOD;

    float *qkv = nullptr, *oh = nullptr;
    __nv_bfloat16 *xhi, *xlo, *wthi, *wtlo, *wohi, *wolo, *ohhi, *ohlo;
    cudaGetSymbolAddress((void**)&qkv,  g_qkv);
    cudaGetSymbolAddress((void**)&oh,   g_oh);
    cudaGetSymbolAddress((void**)&xhi,  g_xhi);
    cudaGetSymbolAddress((void**)&xlo,  g_xlo);
    cudaGetSymbolAddress((void**)&wthi, g_wthi);
    cudaGetSymbolAddress((void**)&wtlo, g_wtlo);
    cudaGetSymbolAddress((void**)&wohi, g_wohi);
    cudaGetSymbolAddress((void**)&wolo, g_wolo);
    cudaGetSymbolAddress((void**)&ohhi, g_ohhi);
    cudaGetSymbolAddress((void**)&ohlo, g_ohlo);

    cudaFuncSetAttribute(attn_kernel,
                         cudaFuncAttributeMaxDynamicSharedMemorySize, AT_SMEM);
    cudaFuncSetAttribute(gemm_hmma_kernel,
                         cudaFuncAttributeMaxDynamicSharedMemorySize, G_SMEM);

    // 0) splits / transposes
    split_kernel<<<(TSEQ * DMOD / 4 + 255) / 256, 256>>>(x, xhi, xlo, TSEQ * DMOD);
    transpose_split_kernel<<<dim3(TRI / 32, DMOD / 32), dim3(32, 8)>>>(
        W, wthi, wtlo, DMOD, TRI);
    transpose_split_kernel<<<dim3(DMOD / 32, DMOD / 32), dim3(32, 8)>>>(
        Wo, wohi, wolo, DMOD, DMOD);

    // 1) qkv = x @ W + b   (HMMA split-bf16)
    gemm_hmma_kernel<<<dim3(TRI / 128, TSEQ / 128), 256, G_SMEM>>>(
        xhi, xlo, wthi, wtlo, b, qkv, TSEQ, TRI, DMOD);

    // 2) k_out / v_out permute
    kv_permute_kernel<<<(TSEQ * DMOD + 255) / 256, 256>>>(qkv, k_out, v_out);

    // 3) fused causal attention with shift bias
    attn_kernel<<<NH * (TSEQ / 64), 256, AT_SMEM>>>(qkv, shift, oh);

    // 4) split attention output, then o = oh @ Wo + bo (HMMA split-bf16)
    split_kernel<<<(TSEQ * DMOD / 4 + 255) / 256, 256>>>(oh, ohhi, ohlo, TSEQ * DMOD);
    gemm_hmma_kernel<<<dim3(DMOD / 128, TSEQ / 128), 256, G_SMEM>>>(
        ohhi, ohlo, wohi, wolo, bo, o_out, TSEQ, DMOD, DMOD);
}

// round 17
// speedup vs baseline: 1.4518x; 1.0008x over previous
#include <cuda_runtime.h>
#include <cuda_bf16.h>
#include <cstdint>

#define TSEQ 2048
#define DMOD 1024
#define NH   16
#define DH   64
#define TRI  3072   // 3*DMOD

// ---------------------------------------------------------------------------
// Scratch (device globals: allocation-free)
// ---------------------------------------------------------------------------
__device__ float g_qkv[TSEQ * TRI];   // [t][h*192 + {q:0,k:64,v:128} + d]
__device__ float g_oh [TSEQ * DMOD];  // attention output, heads concatenated

__device__ __nv_bfloat16 g_xhi [TSEQ * DMOD];
__device__ __nv_bfloat16 g_xlo [TSEQ * DMOD];
__device__ __nv_bfloat16 g_wthi[TRI  * DMOD];   // W^T split: [n][k]
__device__ __nv_bfloat16 g_wtlo[TRI  * DMOD];
__device__ __nv_bfloat16 g_wohi[DMOD * DMOD];   // Wo^T split: [n][k]
__device__ __nv_bfloat16 g_wolo[DMOD * DMOD];
__device__ __nv_bfloat16 g_ohhi[TSEQ * DMOD];
__device__ __nv_bfloat16 g_ohlo[TSEQ * DMOD];

// ---------------------------------------------------------------------------
// helpers
// ---------------------------------------------------------------------------
__device__ __forceinline__ uint32_t smem_u32(const void* p) {
    uint32_t a;
    asm("{ .reg .u64 t; cvta.to.shared.u64 t, %1; cvt.u32.u64 %0, t; }"
        : "=r"(a) : "l"(p));
    return a;
}

#define SW128(off) ((off) ^ (((off) >> 3) & 0x70))

#define CP_ASYNC16(saddr, gptr) \
    asm volatile("cp.async.cg.shared.global [%0], [%1], 16;" \
                 :: "r"((uint32_t)(saddr)), "l"(gptr) : "memory")
#define CP_COMMIT() asm volatile("cp.async.commit_group;" ::: "memory")
#define CP_WAIT(n)  asm volatile("cp.async.wait_group %0;" :: "n"(n) : "memory")

__device__ __forceinline__ void ldsm_x4(uint32_t* r, uint32_t addr) {
    asm volatile("ldmatrix.sync.aligned.m8n8.x4.shared.b16 {%0,%1,%2,%3}, [%4];"
                 : "=r"(r[0]), "=r"(r[1]), "=r"(r[2]), "=r"(r[3]) : "r"(addr));
}

__device__ __forceinline__ void mma_bf16(float* c, const uint32_t* a,
                                         const uint32_t* b) {
    asm volatile(
        "mma.sync.aligned.m16n8k16.row.col.f32.bf16.bf16.f32 "
        "{%0,%1,%2,%3}, {%4,%5,%6,%7}, {%8,%9}, {%0,%1,%2,%3};"
        : "+f"(c[0]), "+f"(c[1]), "+f"(c[2]), "+f"(c[3])
        : "r"(a[0]), "r"(a[1]), "r"(a[2]), "r"(a[3]), "r"(b[0]), "r"(b[1]));
}

// ---------------------------------------------------------------------------
// Split fp32 -> bf16 hi/lo (elementwise, same layout)
// ---------------------------------------------------------------------------
__global__ void split_kernel(const float* __restrict__ in,
                             __nv_bfloat16* __restrict__ hi,
                             __nv_bfloat16* __restrict__ lo, int n)
{
    int i = (blockIdx.x * blockDim.x + threadIdx.x) * 4;
    if (i >= n) return;
    float4 v = *(const float4*)(in + i);
    __nv_bfloat16 h0 = __float2bfloat16(v.x);
    __nv_bfloat16 h1 = __float2bfloat16(v.y);
    __nv_bfloat16 h2 = __float2bfloat16(v.z);
    __nv_bfloat16 h3 = __float2bfloat16(v.w);
    __nv_bfloat162* hp = (__nv_bfloat162*)(hi + i);
    __nv_bfloat162* lp = (__nv_bfloat162*)(lo + i);
    hp[0] = __nv_bfloat162(h0, h1);
    hp[1] = __nv_bfloat162(h2, h3);
    lp[0] = __nv_bfloat162(__float2bfloat16(v.x - __bfloat162float(h0)),
                           __float2bfloat16(v.y - __bfloat162float(h1)));
    lp[1] = __nv_bfloat162(__float2bfloat16(v.z - __bfloat162float(h2)),
                           __float2bfloat16(v.w - __bfloat162float(h3)));
}

// ---------------------------------------------------------------------------
// Transpose + split: in[K][N] fp32 -> out_hi/lo[N][K] bf16
// ---------------------------------------------------------------------------
__global__ void transpose_split_kernel(const float* __restrict__ in,
                                       __nv_bfloat16* __restrict__ ohi,
                                       __nv_bfloat16* __restrict__ olo,
                                       int K, int N)
{
    __shared__ float t[32][33];
    const int bx = blockIdx.x * 32;   // N offset
    const int by = blockIdx.y * 32;   // K offset
    const int x = threadIdx.x, y = threadIdx.y;  // (32, 8)
#pragma unroll
    for (int j = 0; j < 32; j += 8)
        t[y + j][x] = in[(size_t)(by + y + j) * N + bx + x];
    __syncthreads();
#pragma unroll
    for (int j = 0; j < 32; j += 8) {
        float v = t[x][y + j];
        __nv_bfloat16 h = __float2bfloat16(v);
        size_t o = (size_t)(bx + y + j) * K + by + x;
        ohi[o] = h;
        olo[o] = __float2bfloat16(v - __bfloat162float(h));
    }
}

// ---------------------------------------------------------------------------
// HMMA split-bf16 GEMM: C[M,N] = A[M,K] @ Bt[N,K]^T + bias
// CTA: 128x128 tile, BK=64, 2-stage cp.async pipeline, 8 warps (2x4),
// warp tile 64x32, m16n8k16 bf16 MMAs, 3 passes (hi*hi + hi*lo + lo*hi).
// ---------------------------------------------------------------------------
#define G_STAGE (4 * 128 * 64 * 2)        // Ahi,Alo,Bhi,Blo per stage (bytes)
#define G_SMEM  (2 * G_STAGE)             // 131072

__global__ __launch_bounds__(256, 1)
void gemm_hmma_kernel(const __nv_bfloat16* __restrict__ Ahi,
                      const __nv_bfloat16* __restrict__ Alo,
                      const __nv_bfloat16* __restrict__ Bhi,
                      const __nv_bfloat16* __restrict__ Blo,
                      const float* __restrict__ bias,
                      float* __restrict__ C, int M, int N, int K)
{
    extern __shared__ __align__(1024) char smem[];
    const uint32_t sb = smem_u32(smem);

    const int tid  = threadIdx.x;
    const int w    = tid >> 5;
    const int lane = tid & 31;
    const int m0 = blockIdx.y * 128;
    const int n0 = blockIdx.x * 128;

    const int warpM = (w >> 2) * 64;   // 0 / 64
    const int warpN = (w & 3) * 32;    // 0..96

    // ldmatrix per-lane addressing
    const int a_row  = lane & 15;
    const int a_cb   = (lane >> 4) * 16;
    const int b_row  = (lane & 7) + ((lane >> 4) << 3);
    const int b_cb   = ((lane >> 3) & 1) * 16;

    constexpr uint32_t TILE = 128 * 64 * 2;  // 16384 bytes

    float acc[4][4][4];
#pragma unroll
    for (int i = 0; i < 4; i++)
#pragma unroll
        for (int j = 0; j < 4; j++)
#pragma unroll
            for (int q = 0; q < 4; q++) acc[i][j][q] = 0.f;

    const int NK = K >> 6;

    // ---- stage loader ----
    auto load_stage = [&](int chunk, int st) {
        const uint32_t base = sb + st * G_STAGE;
        const int kc = chunk << 6;
#pragma unroll
        for (int it = 0; it < 4; it++) {
            int idx = tid + it * 256;          // 0..1023
            int r = idx >> 3, c = idx & 7;
            uint32_t sw = SW128((uint32_t)(r * 128 + c * 16));
            size_t ga = (size_t)(m0 + r) * K + kc + c * 8;
            size_t gb = (size_t)(n0 + r) * K + kc + c * 8;
            CP_ASYNC16(base + sw,            Ahi + ga);
            CP_ASYNC16(base + TILE + sw,     Alo + ga);
            CP_ASYNC16(base + 2 * TILE + sw, Bhi + gb);
            CP_ASYNC16(base + 3 * TILE + sw, Blo + gb);
        }
        CP_COMMIT();
    };

    load_stage(0, 0);

    for (int i = 0; i < NK; i++) {
        const int st = i & 1;
        if (i + 1 < NK) {
            load_stage(i + 1, st ^ 1);
            CP_WAIT(1);
        } else {
            CP_WAIT(0);
        }
        __syncthreads();

        const uint32_t base = sb + st * G_STAGE;
        const uint32_t sAhi = base;
        const uint32_t sAlo = base + TILE;
        const uint32_t sBhi = base + 2 * TILE;
        const uint32_t sBlo = base + 3 * TILE;

#pragma unroll
        for (int ks = 0; ks < 4; ks++) {
            const int kb = ks * 32;
            uint32_t ah[4][4], al[4][4], bh[2][4], bl[2][4];
#pragma unroll
            for (int mt = 0; mt < 4; mt++) {
                uint32_t off = SW128((uint32_t)((warpM + mt * 16 + a_row) * 128
                                                + kb + a_cb));
                ldsm_x4(ah[mt], sAhi + off);
                ldsm_x4(al[mt], sAlo + off);
            }
#pragma unroll
            for (int np = 0; np < 2; np++) {
                uint32_t off = SW128((uint32_t)((warpN + np * 16 + b_row) * 128
                                                + kb + b_cb));
                ldsm_x4(bh[np], sBhi + off);
                ldsm_x4(bl[np], sBlo + off);
            }
#pragma unroll
            for (int mt = 0; mt < 4; mt++)
#pragma unroll
                for (int nt = 0; nt < 4; nt++) {
                    const uint32_t* bhp = &bh[nt >> 1][(nt & 1) * 2];
                    const uint32_t* blp = &bl[nt >> 1][(nt & 1) * 2];
                    mma_bf16(acc[mt][nt], ah[mt], bhp);   // hi*hi
                    mma_bf16(acc[mt][nt], ah[mt], blp);   // hi*lo
                    mma_bf16(acc[mt][nt], al[mt], bhp);   // lo*hi
                }
        }
        __syncthreads();
    }

    // ---- epilogue: direct fp32 stores + bias ----
    const int er = lane >> 2;
    const int ec = (lane & 3) * 2;
#pragma unroll
    for (int mt = 0; mt < 4; mt++) {
        const int r0 = m0 + warpM + mt * 16 + er;
#pragma unroll
        for (int nt = 0; nt < 4; nt++) {
            const int c = n0 + warpN + nt * 8 + ec;
            float2 bv = *(const float2*)(bias + c);
            float2 v0 = make_float2(acc[mt][nt][0] + bv.x, acc[mt][nt][1] + bv.y);
            float2 v1 = make_float2(acc[mt][nt][2] + bv.x, acc[mt][nt][3] + bv.y);
            *(float2*)(C + (size_t)r0 * N + c)       = v0;
            *(float2*)(C + (size_t)(r0 + 8) * N + c) = v1;
        }
    }
}

// ---------------------------------------------------------------------------
// k_out / v_out permute:  k_out[t][h*64+d] = qkv[t][h*192+64+d], v: +128
// ---------------------------------------------------------------------------
__global__ void kv_permute_kernel(const float* __restrict__ qkv,
                                  float* __restrict__ kout,
                                  float* __restrict__ vout)
{
    int idx = blockIdx.x * blockDim.x + threadIdx.x;
    if (idx >= TSEQ * DMOD) return;
    int t = idx >> 10;
    int col = idx & 1023;
    int h = col >> 6;
    int d = col & 63;
    const float* row = qkv + (size_t)t * TRI + h * 192;
    kout[idx] = row[64 + d];
    vout[idx] = row[128 + d];
}

// ---------------------------------------------------------------------------
// Fused causal attention with per-head shift bias (flash-attention style).
// ---------------------------------------------------------------------------
#define ASTR 68
#define AT_SMEM (4 * 64 * ASTR * 4)

__global__ __launch_bounds__(256)
void attn_kernel(const float* __restrict__ qkv, const float* __restrict__ shift,
                 float* __restrict__ oh)
{
    extern __shared__ float sm[];
    float* QsT = sm;                  // [d][c] swizzled, 64x68
    float* KsT = sm + 64 * ASTR;      // [d][c] swizzled
    float* Vs  = sm + 2 * 64 * ASTR;  // [k][d] natural
    float* Ps  = sm + 3 * 64 * ASTR;  // [r][k] natural

    const int bid = blockIdx.x;
    const int h  = bid & (NH - 1);
    const int qt = 31 - (bid >> 4);       // big q-tiles first (load balance)
    const int q0 = qt * 64;

    const float hscale = exp2f(-0.5f * (float)h);   // exp(-ln2 * h/2)

    const int tid  = threadIdx.x;
    const int w    = tid >> 5, l = tid & 31;
    const int lrow = l >> 4;              // 0..1
    const int lcol = l & 15;              // 0..15
    const int rbase = w * 8 + lrow * 4;   // this thread's 4 q-rows
    const int cbase = lcol * 4;           // this thread's 4 cols
    const int agrp  = rbase >> 2;

    const int dchunk = tid & 15;
    const int crow0  = tid >> 4;

    const float* qb = qkv + h * 192;
    const float* kbp = qb + 64;
    const float* vbp = qb + 128;

    // ---- load Q^T (swizzled) ----
#pragma unroll
    for (int it = 0; it < 4; it++) {
        int c = crow0 + it * 16;
        float4 v = *(const float4*)(qb + (size_t)(q0 + c) * TRI + dchunk * 4);
        int pg = ((c >> 2) ^ dchunk) << 2;
        int base = dchunk * 4 * ASTR + pg + (c & 3);
        QsT[base]            = v.x;
        QsT[base + ASTR]     = v.y;
        QsT[base + 2 * ASTR] = v.z;
        QsT[base + 3 * ASTR] = v.w;
    }

    float o[4][4];
    float mrun[4], lrun[4];
#pragma unroll
    for (int i = 0; i < 4; i++) {
        mrun[i] = -1e30f; lrun[i] = 0.f;
#pragma unroll
        for (int j = 0; j < 4; j++) o[i][j] = 0.f;
    }

    for (int kt = 0; kt <= qt; kt++) {
        const int k0 = kt * 64;
        __syncthreads();

        // ---- load K^T (swizzled) + V (natural) ----
#pragma unroll
        for (int it = 0; it < 4; it++) {
            int c = crow0 + it * 16;
            float4 kv = *(const float4*)(kbp + (size_t)(k0 + c) * TRI + dchunk * 4);
            float4 vv = *(const float4*)(vbp + (size_t)(k0 + c) * TRI + dchunk * 4);
            int pg = ((c >> 2) ^ dchunk) << 2;
            int base = dchunk * 4 * ASTR + pg + (c & 3);
            KsT[base]            = kv.x;
            KsT[base + ASTR]     = kv.y;
            KsT[base + 2 * ASTR] = kv.z;
            KsT[base + 3 * ASTR] = kv.w;
            *(float4*)(Vs + (size_t)c * ASTR + dchunk * 4) = vv;
        }
        __syncthreads();

        // ---- S = Q K^T ----
        float s[4][4];
#pragma unroll
        for (int i = 0; i < 4; i++)
#pragma unroll
            for (int j = 0; j < 4; j++) s[i][j] = 0.f;

#pragma unroll 4
        for (int d = 0; d < 64; d++) {
            int sw = d >> 2;
            float4 a = *(const float4*)(QsT + d * ASTR + ((agrp ^ sw) << 2));
            float4 b = *(const float4*)(KsT + d * ASTR + ((lcol ^ sw) << 2));
            float av[4] = {a.x, a.y, a.z, a.w};
            float bv[4] = {b.x, b.y, b.z, b.w};
#pragma unroll
            for (int i = 0; i < 4; i++)
#pragma unroll
                for (int j = 0; j < 4; j++)
                    s[i][j] = fmaf(av[i], bv[j], s[i][j]);
        }

        // ---- scale, shift bias, causal mask ----
#pragma unroll
        for (int i = 0; i < 4; i++) {
            int gq = q0 + rbase + i;
            float4 sh = *(const float4*)(shift + (size_t)gq * TSEQ + k0 + cbase);
            float shv[4] = {sh.x, sh.y, sh.z, sh.w};
#pragma unroll
            for (int j = 0; j < 4; j++) {
                int gk = k0 + cbase + j;
                float val = fmaf(s[i][j], 0.125f, -hscale * shv[j]);
                s[i][j] = (gk > gq) ? -1e30f : val;
            }
        }

        // ---- online softmax ----
#pragma unroll
        for (int i = 0; i < 4; i++) {
            float tm = fmaxf(fmaxf(s[i][0], s[i][1]), fmaxf(s[i][2], s[i][3]));
            tm = fmaxf(tm, __shfl_xor_sync(0xffffffffu, tm, 1));
            tm = fmaxf(tm, __shfl_xor_sync(0xffffffffu, tm, 2));
            tm = fmaxf(tm, __shfl_xor_sync(0xffffffffu, tm, 4));
            tm = fmaxf(tm, __shfl_xor_sync(0xffffffffu, tm, 8));
            float mnew = fmaxf(mrun[i], tm);
            float alpha = __expf(mrun[i] - mnew);
            float rs = 0.f;
#pragma unroll
            for (int j = 0; j < 4; j++) {
                float p = __expf(s[i][j] - mnew);
                s[i][j] = p;
                rs += p;
            }
            rs += __shfl_xor_sync(0xffffffffu, rs, 1);
            rs += __shfl_xor_sync(0xffffffffu, rs, 2);
            rs += __shfl_xor_sync(0xffffffffu, rs, 4);
            rs += __shfl_xor_sync(0xffffffffu, rs, 8);
            lrun[i] = lrun[i] * alpha + rs;
            mrun[i] = mnew;
#pragma unroll
            for (int j = 0; j < 4; j++) o[i][j] *= alpha;
        }

        // ---- P -> smem ----
#pragma unroll
        for (int i = 0; i < 4; i++)
            *(float4*)(Ps + (size_t)(rbase + i) * ASTR + cbase) =
                make_float4(s[i][0], s[i][1], s[i][2], s[i][3]);
        __syncthreads();

        // ---- O += P @ V ----
#pragma unroll 4
        for (int k4 = 0; k4 < 64; k4 += 4) {
            float4 pa0 = *(const float4*)(Ps + (size_t)(rbase + 0) * ASTR + k4);
            float4 pa1 = *(const float4*)(Ps + (size_t)(rbase + 1) * ASTR + k4);
            float4 pa2 = *(const float4*)(Ps + (size_t)(rbase + 2) * ASTR + k4);
            float4 pa3 = *(const float4*)(Ps + (size_t)(rbase + 3) * ASTR + k4);
            float pm[4][4] = {
                {pa0.x, pa0.y, pa0.z, pa0.w},
                {pa1.x, pa1.y, pa1.z, pa1.w},
                {pa2.x, pa2.y, pa2.z, pa2.w},
                {pa3.x, pa3.y, pa3.z, pa3.w}};
#pragma unroll
            for (int kk = 0; kk < 4; kk++) {
                float4 b = *(const float4*)(Vs + (size_t)(k4 + kk) * ASTR + cbase);
                float bv[4] = {b.x, b.y, b.z, b.w};
#pragma unroll
                for (int i = 0; i < 4; i++) {
                    float p = pm[i][kk];
#pragma unroll
                    for (int j = 0; j < 4; j++)
                        o[i][j] = fmaf(p, bv[j], o[i][j]);
                }
            }
        }
    }

    // ---- finalize ----
#pragma unroll
    for (int i = 0; i < 4; i++) {
        float inv = 1.f / lrun[i];
        int gq = q0 + rbase + i;
        float4 v = make_float4(o[i][0] * inv, o[i][1] * inv,
                               o[i][2] * inv, o[i][3] * inv);
        *(float4*)(oh + (size_t)gq * DMOD + h * DH + cbase) = v;
    }
}

// ---------------------------------------------------------------------------
extern "C" void kernel_launch(void* const* d_in, const int* in_sizes, int n_in,
                              void* d_out, int out_size)
{
    (void)in_sizes; (void)n_in; (void)out_size;

    const float* x     = (const float*)d_in[0];
    // d_in[1] = mask: always causal tril by construction -> computed from indices
    const float* shift = (const float*)d_in[2];
    const float* W     = (const float*)d_in[3];
    const float* b     = (const float*)d_in[4];
    const float* Wo    = (const float*)d_in[5];
    const float* bo    = (const float*)d_in[6];

    float* out   = (float*)d_out;
    float* o_out = out;
    float* k_out = out + (size_t)TSEQ * DMOD;
    float* v_out = out + 2 * (size_t)TSEQ * DMOD;

    float *qkv = nullptr, *oh = nullptr;
    __nv_bfloat16 *xhi, *xlo, *wthi, *wtlo, *wohi, *wolo, *ohhi, *ohlo;
    cudaGetSymbolAddress((void**)&qkv,  g_qkv);
    cudaGetSymbolAddress((void**)&oh,   g_oh);
    cudaGetSymbolAddress((void**)&xhi,  g_xhi);
    cudaGetSymbolAddress((void**)&xlo,  g_xlo);
    cudaGetSymbolAddress((void**)&wthi, g_wthi);
    cudaGetSymbolAddress((void**)&wtlo, g_wtlo);
    cudaGetSymbolAddress((void**)&wohi, g_wohi);
    cudaGetSymbolAddress((void**)&wolo, g_wolo);
    cudaGetSymbolAddress((void**)&ohhi, g_ohhi);
    cudaGetSymbolAddress((void**)&ohlo, g_ohlo);

    cudaFuncSetAttribute(attn_kernel,
                         cudaFuncAttributeMaxDynamicSharedMemorySize, AT_SMEM);
    cudaFuncSetAttribute(gemm_hmma_kernel,
                         cudaFuncAttributeMaxDynamicSharedMemorySize, G_SMEM);

    // 0) splits / transposes
    split_kernel<<<(TSEQ * DMOD / 4 + 255) / 256, 256>>>(x, xhi, xlo, TSEQ * DMOD);
    transpose_split_kernel<<<dim3(TRI / 32, DMOD / 32), dim3(32, 8)>>>(
        W, wthi, wtlo, DMOD, TRI);
    transpose_split_kernel<<<dim3(DMOD / 32, DMOD / 32), dim3(32, 8)>>>(
        Wo, wohi, wolo, DMOD, DMOD);

    // 1) qkv = x @ W + b   (HMMA split-bf16)
    gemm_hmma_kernel<<<dim3(TRI / 128, TSEQ / 128), 256, G_SMEM>>>(
        xhi, xlo, wthi, wtlo, b, qkv, TSEQ, TRI, DMOD);

    // 2) k_out / v_out permute
    kv_permute_kernel<<<(TSEQ * DMOD + 255) / 256, 256>>>(qkv, k_out, v_out);

    // 3) fused causal attention with shift bias
    attn_kernel<<<NH * (TSEQ / 64), 256, AT_SMEM>>>(qkv, shift, oh);

    // 4) split attention output, then o = oh @ Wo + bo (HMMA split-bf16)
    split_kernel<<<(TSEQ * DMOD / 4 + 255) / 256, 256>>>(oh, ohhi, ohlo, TSEQ * DMOD);
    gemm_hmma_kernel<<<dim3(DMOD / 128, TSEQ / 128), 256, G_SMEM>>>(
        ohhi, ohlo, wohi, wolo, bo, o_out, TSEQ, DMOD, DMOD);
}